// round 6
// baseline (speedup 1.0000x reference)
#include <cuda_runtime.h>
#include <cuda_fp16.h>
#include <cstdint>

#define IN_DIM 1024     // 2*L1
#define LXD    32
#define NBUCK  8
#define MAXB   65536
#define BK     32       // K per pipeline step
#define MTILE  128
#define NTHR   128
#define NSTEP  (IN_DIM / BK)   // 32
#define XSTR   40       // Xs row stride in floats
#define WLSCALE 2048.0f // 2^11 scale for weight low part

// ---------------- device scratch ----------------
// Weight fragments: [b][step][split(wh/wl)][kf][nf][lane*2+r] as u32 fp16x2 pairs
__device__ uint32_t g_Wfrag[NBUCK * 32 * 2 * 2 * 4 * 64];   // 1 MB
__device__ int      g_cnt[NBUCK];      // zero-init; restored to 0 by main_kernel
__device__ int      g_list[NBUCK * MAXB];
__device__ int      g_done;            // CTA completion counter for reset

// ---------------- PTX helpers ----------------
__device__ __forceinline__ unsigned sptr(const void* p) {
    return (unsigned)__cvta_generic_to_shared(p);
}
__device__ __forceinline__ void cp16(void* dst, const void* src) {
    asm volatile("cp.async.cg.shared.global [%0], [%1], 16;\n" :: "r"(sptr(dst)), "l"(src));
}
__device__ __forceinline__ void cp_commit() { asm volatile("cp.async.commit_group;\n"); }
template<int N> __device__ __forceinline__ void cp_wait() {
    asm volatile("cp.async.wait_group %0;\n" :: "n"(N));
}
// pack two f32 -> f16x2 (upper = hi_src, lower = lo_src)
__device__ __forceinline__ uint32_t f16pack(float hi_src, float lo_src) {
    uint32_t r;
    asm("cvt.rn.f16x2.f32 %0, %1, %2;" : "=r"(r) : "f"(hi_src), "f"(lo_src));
    return r;
}
__device__ __forceinline__ void mma_f16(float c[4], const uint32_t a[4],
                                        uint32_t b0, uint32_t b1) {
    asm("mma.sync.aligned.m16n8k16.row.col.f32.f16.f16.f32 "
        "{%0,%1,%2,%3},{%4,%5,%6,%7},{%8,%9},{%0,%1,%2,%3};"
        : "+f"(c[0]), "+f"(c[1]), "+f"(c[2]), "+f"(c[3])
        : "r"(a[0]), "r"(a[1]), "r"(a[2]), "r"(a[3]), "r"(b0), "r"(b1));
}

// ---------------- kernel 1: fused weight-fragment prep + row binning ----------------
// ls_indices is int32 on the wire (JAX x64 disabled).
__global__ void prep_kernel(const float* __restrict__ w0, const float* __restrict__ w_fact,
                            const int* __restrict__ ls, int B) {
    int tid = blockIdx.x * blockDim.x + threadIdx.x;

    // --- weight fragments: fp16 hi + scaled-lo, mma-fragment ordered ---
    if (tid < NBUCK * LXD * 512) {
        int kp = tid & 511;            // k pair index
        int j  = (tid >> 9) & 31;      // output column n
        int b  = tid >> 14;            // bucket
        int k0 = kp * 2;
        float x0 = w0[(b * LXD + j) * IN_DIM + k0]     + w_fact[j * IN_DIM + k0];
        float x1 = w0[(b * LXD + j) * IN_DIM + k0 + 1] + w_fact[j * IN_DIM + k0 + 1];
        uint32_t h = f16pack(x1, x0);
        __half2 hh = *reinterpret_cast<__half2*>(&h);
        float e0 = (x0 - __low2float(hh))  * WLSCALE;
        float e1 = (x1 - __high2float(hh)) * WLSCALE;
        uint32_t l = f16pack(e1, e0);
        int step = k0 >> 5, kk = k0 & 31;
        int kf = kk >> 4, kr = kk & 15;
        int r = kr >> 3;
        int lane = ((j & 7) << 2) + ((kr & 7) >> 1);
        int nf = j >> 3;
        int base = ((((b * 32 + step) * 2 + 0) * 2 + kf) * 4 + nf) * 64 + lane * 2 + r;
        g_Wfrag[base]       = h;       // split 0 (wh)
        g_Wfrag[base + 512] = l;       // split 1 (wl * 2^11)
    }

    // --- bin rows by bucket (warp-aggregated atomics; g_cnt is 0 on entry) ---
    if (tid < B) {
        int b = ls[tid] & (NBUCK - 1);
        unsigned active = __activemask();
        unsigned m = __match_any_sync(active, b);
        int lane = threadIdx.x & 31;
        int leader = __ffs(m) - 1;
        int rank = __popc(m & ((1u << lane) - 1u));
        int base = 0;
        if (lane == leader) base = atomicAdd(&g_cnt[b], __popc(m));
        base = __shfl_sync(m, base, leader);
        g_list[b * MAXB + base + rank] = tid;
    }
}

// ---------------- kernel 2: tensor-core binned GEMM + fused MLP ----------------
struct __align__(16) Smem {
    float    Xs[2][MTILE][XSTR];      // fp32 x tiles (double buffered)  40960 B
    uint32_t Ws[2][1024];             // weight fragments, one K-step (wh+wl)  8192 B
    const float* xptr[MTILE];
    int   perm[MTILE];
    float w1T[LXD * LXD];
    float b0s[LXD], b1s[LXD], w2s[LXD];
    float b2s;
};

__device__ __forceinline__ void process_row(const Smem* S, const float* hrow,
                                            int row, float* __restrict__ out) {
    if (row < 0) return;
    float h2[LXD];
#pragma unroll
    for (int j = 0; j < LXD; ++j) h2[j] = S->b1s[j];
#pragma unroll
    for (int i = 0; i < LXD; ++i) {
        float xi = hrow[i] + S->b0s[i];
        xi = fminf(fmaxf(xi, 0.0f), 1.0f);
        const float* wr = &S->w1T[i * LXD];
#pragma unroll
        for (int j = 0; j < LXD; ++j) h2[j] = fmaf(xi, wr[j], h2[j]);
    }
    float o = S->b2s;
#pragma unroll
    for (int j = 0; j < LXD; ++j) {
        float c = fminf(fmaxf(h2[j], 0.0f), 1.0f);
        o = fmaf(c, S->w2s[j], o);
    }
    out[row] = o;
}

__device__ __forceinline__ void build_a16(const float* xp, uint32_t a[4]) {
    float2 p0 = *reinterpret_cast<const float2*>(xp);                 // row g,   k lo
    float2 p1 = *reinterpret_cast<const float2*>(xp + 8 * XSTR);      // row g+8, k lo
    float2 p2 = *reinterpret_cast<const float2*>(xp + 8);             // row g,   k hi
    float2 p3 = *reinterpret_cast<const float2*>(xp + 8 * XSTR + 8);  // row g+8, k hi
    a[0] = f16pack(p0.y, p0.x);
    a[1] = f16pack(p1.y, p1.x);
    a[2] = f16pack(p2.y, p2.x);
    a[3] = f16pack(p3.y, p3.x);
}

__global__ void __launch_bounds__(NTHR, 4)
main_kernel(const float* __restrict__ x,
            const float* __restrict__ b0, const float* __restrict__ b1,
            const float* __restrict__ w1, const float* __restrict__ w2,
            const float* __restrict__ b2,
            float* __restrict__ out, int B) {
    extern __shared__ char smem_raw[];
    Smem* S = reinterpret_cast<Smem*>(smem_raw);

    const int tile = blockIdx.x;
    const int b    = blockIdx.y;
    const int cnt  = g_cnt[b];
    const int start = tile * MTILE;
    const int t    = threadIdx.x;

    if (start < cnt) {
        const int lane = t & 31;
        const int warp = t >> 5;
        const int g    = lane >> 2;
        const int tq   = lane & 3;
        const int wrow = warp * 32;

        // ---- stage per-CTA metadata + small weights ----
        {
            int gi = start + t;
            int ridx = (gi < cnt) ? g_list[b * MAXB + gi] : -1;
            S->perm[t] = ridx;
            S->xptr[t] = x + (size_t)(ridx < 0 ? 0 : ridx) * IN_DIM;
        }
        for (int idx = t; idx < LXD * LXD; idx += NTHR) {
            int i = idx >> 5, j = idx & 31;
            S->w1T[idx] = w1[(b * LXD + j) * LXD + i];
        }
        if (t < LXD) {
            S->b0s[t] = b0[b * LXD + t];
            S->b1s[t] = b1[b * LXD + t];
            S->w2s[t] = w2[b * LXD + t];
        }
        if (t == 32) S->b2s = b2[b];
        __syncthreads();

        const uint32_t* wfrag = g_Wfrag + ((size_t)(b * 32) << 10);
        const int k4 = t & 7;
        const int rb = t >> 3;

        auto load_step = [&](int stage, int s) {
            int k0 = s * BK;
#pragma unroll
            for (int p = 0; p < MTILE / 16; ++p) {
                int r = p * 16 + rb;
                cp16(&S->Xs[stage][r][k4 * 4], S->xptr[r] + k0 + k4 * 4);
            }
            const uint32_t* wsrc = wfrag + (s << 10) + t * 8;
            uint32_t* wdst = &S->Ws[stage][t * 8];
            cp16(wdst, wsrc);
            cp16(wdst + 4, wsrc + 4);
            cp_commit();
        };

        float cH[2][4][4], cL[2][4][4];
#pragma unroll
        for (int mf = 0; mf < 2; ++mf)
#pragma unroll
            for (int nf = 0; nf < 4; ++nf)
#pragma unroll
                for (int q = 0; q < 4; ++q) { cH[mf][nf][q] = 0.0f; cL[mf][nf][q] = 0.0f; }

        load_step(0, 0);

#pragma unroll 1
        for (int s = 0; s < NSTEP; ++s) {
            const int stage = s & 1;
            cp_wait<0>();
            __syncthreads();                 // single barrier per step
            if (s + 1 < NSTEP) load_step(stage ^ 1, s + 1);

#pragma unroll
            for (int kf = 0; kf < 2; ++kf) {
                uint32_t a0[4], a1[4];
                build_a16(&S->Xs[stage][wrow + g][kf * 16 + 2 * tq], a0);
                build_a16(&S->Xs[stage][wrow + 16 + g][kf * 16 + 2 * tq], a1);
                const uint32_t* wsb = S->Ws[stage];
#pragma unroll
                for (int nf = 0; nf < 4; ++nf) {
                    uint2 bh = *reinterpret_cast<const uint2*>(wsb + (kf * 4 + nf) * 64 + lane * 2);
                    uint2 bl = *reinterpret_cast<const uint2*>(wsb + ((2 + kf) * 4 + nf) * 64 + lane * 2);
                    mma_f16(cH[0][nf], a0, bh.x, bh.y);
                    mma_f16(cL[0][nf], a0, bl.x, bl.y);
                    mma_f16(cH[1][nf], a1, bh.x, bh.y);
                    mma_f16(cL[1][nf], a1, bl.x, bl.y);
                }
            }
        }
        __syncthreads();   // all compute done before reusing Xs[0]

        // ---- combine splits, write layer-0 result to smem (reuse Xs[0]) ----
        float (*Hs)[XSTR] = S->Xs[0];
        const float inv = 1.0f / WLSCALE;
#pragma unroll
        for (int mf = 0; mf < 2; ++mf)
#pragma unroll
            for (int nf = 0; nf < 4; ++nf) {
                int r0 = wrow + mf * 16 + g;
                int j0 = nf * 8 + 2 * tq;
                *reinterpret_cast<float2*>(&Hs[r0][j0]) = make_float2(
                    fmaf(cL[mf][nf][0], inv, cH[mf][nf][0]),
                    fmaf(cL[mf][nf][1], inv, cH[mf][nf][1]));
                *reinterpret_cast<float2*>(&Hs[r0 + 8][j0]) = make_float2(
                    fmaf(cL[mf][nf][2], inv, cH[mf][nf][2]),
                    fmaf(cL[mf][nf][3], inv, cH[mf][nf][3]));
            }
        __syncthreads();

        // ---- fused layer1 + layer2 epilogue (1 row / thread) ----
        process_row(S, Hs[t], S->perm[t], out);
    }

    // ---- last-CTA reset of counters for the next graph replay ----
    if (t == 0) {
        __threadfence();
        int total = gridDim.x * gridDim.y;
        int old = atomicAdd(&g_done, 1);
        if (old == total - 1) {
#pragma unroll
            for (int i = 0; i < NBUCK; ++i) g_cnt[i] = 0;
            __threadfence();
            g_done = 0;
        }
    }
}

// ---------------- launch ----------------
extern "C" void kernel_launch(void* const* d_in, const int* in_sizes, int n_in,
                              void* d_out, int out_size) {
    const float* x      = (const float*)d_in[0];
    const int*   ls     = (const int*)d_in[1];
    const float* w_fact = (const float*)d_in[2];
    const float* w0     = (const float*)d_in[3];
    const float* b0     = (const float*)d_in[4];
    const float* w1     = (const float*)d_in[5];
    const float* b1     = (const float*)d_in[6];
    const float* w2     = (const float*)d_in[7];
    const float* b2     = (const float*)d_in[8];
    float*       out    = (float*)d_out;

    const int B = in_sizes[0] / IN_DIM;

    prep_kernel<<<(NBUCK * LXD * 512 + 255) / 256, 256>>>(w0, w_fact, ls, B);

    static const size_t smem_bytes = sizeof(Smem);
    cudaFuncSetAttribute(main_kernel, cudaFuncAttributeMaxDynamicSharedMemorySize,
                         (int)smem_bytes);
    dim3 grid((B + MTILE - 1) / MTILE, NBUCK);
    main_kernel<<<grid, NTHR, smem_bytes>>>(x, b0, b1, w1, w2, b2, out, B);
}